// round 4
// baseline (speedup 1.0000x reference)
#include <cuda_runtime.h>

#define T_DIM   2000
#define KFR     400
#define KD      400
#define A_DIM   100
#define TSPLIT  25
#define TCHUNK  (T_DIM / TSPLIT)       // 80 rows per block
#define NB      (TCHUNK / 16)          // 5 batches of 16 t-rows per block
#define EPSF    1e-24f

// Accumulators: [0..99]=Ga, [100..199]=Ha, [200]=P1, [201]=P2.
// Self-cleaning: finalize zeroes after reading, so every kernel_launch call
// (and every graph replay) starts from 0 without a dedicated memset launch.
__device__ float d_acc[2 * A_DIM + 2];

// One block per (split, k). Each warp owns 4 consecutive t-rows per batch:
// packed butterfly (9 shfl / 4 rows) leaves row dot-products in disjoint
// 8-lane groups, so exp/log/div run once per group (1 MUFU op serves 4 rows).
// Software-pipelined loads keep 4 LDG.128/warp in flight. X_fr read once.
// Epilogue applies the phi_fr weighting and atomically folds into d_acc.
__global__ __launch_bounds__(128) void mmdglm_main(
    const float* __restrict__ tg, const int* __restrict__ mask,
    const float* __restrict__ X, const float* __restrict__ theta,
    const float* __restrict__ phi_fr)
{
    const int k     = blockIdx.y;
    const int split = blockIdx.x;
    const int warp  = threadIdx.x >> 5;
    const int lane  = threadIdx.x & 31;
    const float dt  = tg[1] - tg[0];
    const unsigned FULL = 0xffffffffu;

    float4 th = make_float4(0.f, 0.f, 0.f, 0.f);
    if (lane < 25) th = __ldg(((const float4*)theta) + lane);

    // lane's 8-lane group maps to row: lanes 0-7 -> r0, 8-15 -> r2,
    // 16-23 -> r1, 24-31 -> r3 (from the packed butterfly below)
    const int myrow = (((lane >> 3) & 1) << 1) | ((lane >> 4) & 1);

    float g0 = 0.f, g1 = 0.f, g2 = 0.f, g3 = 0.f, llacc = 0.f;

    const int tbase = split * TCHUNK + warp * 4;
    const size_t RS = (size_t)KFR * A_DIM;

    // prefetch batch 0
    float4 z = make_float4(0.f, 0.f, 0.f, 0.f);
    float4 c0 = z, c1 = z, c2 = z, c3 = z;
    {
        const float* rowp = X + ((size_t)tbase * KFR + k) * A_DIM;
        if (lane < 25) {
            c0 = __ldg((const float4*)(rowp)          + lane);
            c1 = __ldg((const float4*)(rowp + RS)     + lane);
            c2 = __ldg((const float4*)(rowp + 2 * RS) + lane);
            c3 = __ldg((const float4*)(rowp + 3 * RS) + lane);
        }
    }
    int mcur = __ldg(mask + (size_t)(tbase + myrow) * KFR + k);

    #pragma unroll 1
    for (int b = 0; b < NB; b++) {
        float4 n0 = z, n1 = z, n2 = z, n3 = z;
        int mnext = 0;
        if (b + 1 < NB) {
            const int tn = tbase + (b + 1) * 16;
            const float* rowp = X + ((size_t)tn * KFR + k) * A_DIM;
            if (lane < 25) {
                n0 = __ldg((const float4*)(rowp)          + lane);
                n1 = __ldg((const float4*)(rowp + RS)     + lane);
                n2 = __ldg((const float4*)(rowp + 2 * RS) + lane);
                n3 = __ldg((const float4*)(rowp + 3 * RS) + lane);
            }
            mnext = __ldg(mask + (size_t)(tn + myrow) * KFR + k);
        }

        float p0 = c0.x * th.x + c0.y * th.y + c0.z * th.z + c0.w * th.w;
        float p1 = c1.x * th.x + c1.y * th.y + c1.z * th.z + c1.w * th.w;
        float p2 = c2.x * th.x + c2.y * th.y + c2.z * th.z + c2.w * th.w;
        float p3 = c3.x * th.x + c3.y * th.y + c3.z * th.z + c3.w * th.w;

        // Packed butterfly: 9 shfl reduce all 4 rows.
        float u0 = __shfl_xor_sync(FULL, p0, 16);
        float u1 = __shfl_xor_sync(FULL, p1, 16);
        float w01 = (lane & 16) ? (p1 + u1) : (p0 + u0);
        float u2 = __shfl_xor_sync(FULL, p2, 16);
        float u3 = __shfl_xor_sync(FULL, p3, 16);
        float w23 = (lane & 16) ? (p3 + u3) : (p2 + u2);
        float v01 = __shfl_xor_sync(FULL, w01, 8);
        float v23 = __shfl_xor_sync(FULL, w23, 8);
        float v = (lane & 8) ? (w23 + v23) : (w01 + v01);
        v += __shfl_xor_sync(FULL, v, 4);
        v += __shfl_xor_sync(FULL, v, 2);
        v += __shfl_xor_sync(FULL, v, 1);
        // v = dot of row (t0 + myrow)

        const float r   = __expf(v);            // non_linearity = exp
        const float dtr = dt * r;
        float w, llc;
        if (mcur) {
            const float E = __expf(dtr);
            w   = __fdividef(dtr, E - 1.0f - EPSF);
            llc = __logf(1.0f - __expf(-dtr) + EPSF);
        } else {
            w   = -dtr;
            llc = -dtr;
        }
        llacc += llc;                            // 8x redundant; /8 at epilogue

        const float w0 = __shfl_sync(FULL, w, 0);
        const float w1 = __shfl_sync(FULL, w, 16);
        const float w2 = __shfl_sync(FULL, w, 8);
        const float w3 = __shfl_sync(FULL, w, 24);

        g0 += w0 * c0.x + w1 * c1.x + w2 * c2.x + w3 * c3.x;
        g1 += w0 * c0.y + w1 * c1.y + w2 * c2.y + w3 * c3.y;
        g2 += w0 * c0.z + w1 * c1.z + w2 * c2.z + w3 * c3.z;
        g3 += w0 * c0.w + w1 * c1.w + w2 * c2.w + w3 * c3.w;

        c0 = n0; c1 = n1; c2 = n2; c3 = n3; mcur = mnext;
    }

    #pragma unroll
    for (int o = 16; o; o >>= 1) llacc += __shfl_xor_sync(FULL, llacc, o);
    llacc *= 0.125f;

    __shared__ float sg[4][A_DIM];
    __shared__ float sll[4];
    if (lane < 25) *(float4*)&sg[warp][lane * 4] = make_float4(g0, g1, g2, g3);
    if (lane == 0) sll[warp] = llacc;
    __syncthreads();

    const float pf = __ldg(phi_fr + k);
    const int tid = threadIdx.x;
    if (tid < A_DIM) {
        const float s = sg[0][tid] + sg[1][tid] + sg[2][tid] + sg[3][tid];
        atomicAdd(&d_acc[tid],         pf * s);        // Ga
        atomicAdd(&d_acc[A_DIM + tid], pf * pf * s);   // Ha
    }
    if (tid == 0) {
        const float llb = sll[0] + sll[1] + sll[2] + sll[3];
        atomicAdd(&d_acc[2 * A_DIM],     pf * llb);        // P1
        atomicAdd(&d_acc[2 * A_DIM + 1], pf * pf * llb);   // P2
    }
}

// Rank-1 gramians: only phi moments + the accumulated Ga/Ha/P1/P2 remain.
// Reads d_acc into registers, then zeroes it for the next launch/replay.
__global__ __launch_bounds__(128) void mmdglm_finalize(
    const float* __restrict__ phi_d, const float* __restrict__ phi_fr,
    float* __restrict__ out)
{
    __shared__ float shp[4][4];
    __shared__ float sc[4];
    const int tid = threadIdx.x, lane = tid & 31, warp = tid >> 5;
    const unsigned FULL = 0xffffffffu;

    // snapshot accumulators before cleaning
    float Ga = 0.f, Ha = 0.f;
    if (tid < A_DIM) { Ga = d_acc[tid]; Ha = d_acc[A_DIM + tid]; }
    const float P1 = d_acc[2 * A_DIM], P2 = d_acc[2 * A_DIM + 1];

    float a0 = 0.f, a1 = 0.f, a2 = 0.f, a3 = 0.f;
    for (int i = tid; i < KFR; i += 128) {
        const float pf = phi_fr[i], pd = phi_d[i];
        a0 += pf; a1 += pf * pf; a2 += pd; a3 += pd * pd;
    }
    #pragma unroll
    for (int o = 16; o; o >>= 1) {
        a0 += __shfl_xor_sync(FULL, a0, o);
        a1 += __shfl_xor_sync(FULL, a1, o);
        a2 += __shfl_xor_sync(FULL, a2, o);
        a3 += __shfl_xor_sync(FULL, a3, o);
    }
    if (lane == 0) { shp[warp][0] = a0; shp[warp][1] = a1;
                     shp[warp][2] = a2; shp[warp][3] = a3; }
    __syncthreads();

    // clean d_acc for the next graph replay (all reads above are done)
    if (tid < A_DIM) { d_acc[tid] = 0.f; d_acc[A_DIM + tid] = 0.f; }
    if (tid == A_DIM) { d_acc[2 * A_DIM] = 0.f; d_acc[2 * A_DIM + 1] = 0.f; }

    if (tid < 4) sc[tid] = shp[0][tid] + shp[1][tid] + shp[2][tid] + shp[3][tid];
    __syncthreads();

    const float S_fr = sc[0], Q_fr = sc[1], S_d = sc[2], Q_d = sc[3];
    const float n_fr = 0.5f * (float)KFR * (float)(KFR - 1);
    const float n_d  = 0.5f * (float)KD  * (float)(KD - 1);
    const float inv_kdkfr = 1.0f / ((float)KD * (float)KFR);

    if (tid == 0) {
        out[0] = (P1 * S_fr - P2) / n_fr - 2.0f * S_d * P1 * inv_kdkfr;
        out[1 + A_DIM] = (S_d * S_d - Q_d) / (2.0f * n_d)
                       + (S_fr * S_fr - Q_fr) / (2.0f * n_fr)
                       - 2.0f * S_d * S_fr * inv_kdkfr;
    }
    if (tid < A_DIM) {
        out[1 + tid] = (S_fr * Ga - Ha) / n_fr - 2.0f * S_d * Ga * inv_kdkfr;
    }
}

extern "C" void kernel_launch(void* const* d_in, const int* in_sizes, int n_in,
                              void* d_out, int out_size) {
    const float* t      = (const float*)d_in[0];
    const int*   mask   = (const int*)  d_in[1];
    const float* X      = (const float*)d_in[2];
    const float* theta  = (const float*)d_in[3];
    const float* phi_d  = (const float*)d_in[4];
    const float* phi_fr = (const float*)d_in[5];
    float* out = (float*)d_out;

    dim3 grid(TSPLIT, KFR);
    mmdglm_main<<<grid, 128>>>(t, mask, X, theta, phi_fr);
    mmdglm_finalize<<<1, 128>>>(phi_d, phi_fr, out);
}

// round 5
// speedup vs baseline: 1.8271x; 1.8271x over previous
#include <cuda_runtime.h>

#define T_DIM   2000
#define KFR     400
#define KD      400
#define A_DIM   100
#define NB      (KFR / 16)             // 25 batches of 16 k-rows per block
#define EPSF    1e-24f

// Accumulators: [0..99]=Ga, [100..199]=Ha, [200]=P1, [201]=P2.
// Self-cleaning: finalize zeroes after reading, so every launch/replay
// starts from 0 without a dedicated memset kernel.
__device__ float d_acc[2 * A_DIM + 2];

// One block per time index t. The block consumes the CONTIGUOUS 160KB slab
// X[t,:,:]; warp w handles rows k = b*16 + w*4 + {0..3} in batch b, so the
// block's in-flight loads always cover an adjacent ~26KB window that slides
// forward — streaming-friendly for HBM row buffers (vs. the old 160KB-stride
// per-warp walk). phi_fr is folded at the row level, which is what removes
// the need for any per-k accumulator:
//   Ga[a]=sum pf_k*w*x, Ha[a]=sum pf_k^2*w*x, P1=sum pf_k*llc, P2=sum pf^2*llc.
// Packed butterfly: 9 shfl reduce 4 row-dots, leaving each dot in a disjoint
// 8-lane group so exp/log/div run once per group (1 MUFU op serves 4 rows).
__global__ __launch_bounds__(128) void mmdglm_main(
    const float* __restrict__ tg, const int* __restrict__ mask,
    const float* __restrict__ X, const float* __restrict__ theta,
    const float* __restrict__ phi_fr)
{
    const int t     = blockIdx.x;
    const int warp  = threadIdx.x >> 5;
    const int lane  = threadIdx.x & 31;
    const float dt  = tg[1] - tg[0];
    const unsigned FULL = 0xffffffffu;

    float4 th = make_float4(0.f, 0.f, 0.f, 0.f);
    if (lane < 25) th = __ldg(((const float4*)theta) + lane);

    // packed-butterfly group -> row: lanes 0-7 r0, 8-15 r2, 16-23 r1, 24-31 r3
    const int myrow = (((lane >> 3) & 1) << 1) | ((lane >> 4) & 1);

    float Ga0 = 0.f, Ga1 = 0.f, Ga2 = 0.f, Ga3 = 0.f;
    float Ha0 = 0.f, Ha1 = 0.f, Ha2 = 0.f, Ha3 = 0.f;
    float p1acc = 0.f, p2acc = 0.f;

    const float* slab = X + (size_t)t * KFR * A_DIM;   // contiguous 160KB
    const int*   mrow = mask + (size_t)t * KFR;

    // prefetch batch 0 (kbase = warp*4)
    float4 z = make_float4(0.f, 0.f, 0.f, 0.f);
    float4 c0 = z, c1 = z, c2 = z, c3 = z;
    {
        const float* rowp = slab + (warp * 4) * A_DIM;
        if (lane < 25) {
            c0 = __ldg((const float4*)(rowp)             + lane);
            c1 = __ldg((const float4*)(rowp + A_DIM)     + lane);
            c2 = __ldg((const float4*)(rowp + 2 * A_DIM) + lane);
            c3 = __ldg((const float4*)(rowp + 3 * A_DIM) + lane);
        }
    }
    int mcur = __ldg(mrow + warp * 4 + myrow);

    #pragma unroll 1
    for (int b = 0; b < NB; b++) {
        const int kbase = b * 16 + warp * 4;

        float4 n0 = z, n1 = z, n2 = z, n3 = z;
        int mnext = 0;
        if (b + 1 < NB) {
            const int kn = kbase + 16;
            const float* rowp = slab + kn * A_DIM;
            if (lane < 25) {
                n0 = __ldg((const float4*)(rowp)             + lane);
                n1 = __ldg((const float4*)(rowp + A_DIM)     + lane);
                n2 = __ldg((const float4*)(rowp + 2 * A_DIM) + lane);
                n3 = __ldg((const float4*)(rowp + 3 * A_DIM) + lane);
            }
            mnext = __ldg(mrow + kn + myrow);
        }

        // per-row phi (uniform-address loads, L1-resident 1.6KB table)
        const float pf0 = __ldg(phi_fr + kbase);
        const float pf1 = __ldg(phi_fr + kbase + 1);
        const float pf2 = __ldg(phi_fr + kbase + 2);
        const float pf3 = __ldg(phi_fr + kbase + 3);

        float p0 = c0.x * th.x + c0.y * th.y + c0.z * th.z + c0.w * th.w;
        float p1 = c1.x * th.x + c1.y * th.y + c1.z * th.z + c1.w * th.w;
        float p2 = c2.x * th.x + c2.y * th.y + c2.z * th.z + c2.w * th.w;
        float p3 = c3.x * th.x + c3.y * th.y + c3.z * th.z + c3.w * th.w;

        // Packed butterfly: 9 shfl reduce all 4 rows.
        float u0 = __shfl_xor_sync(FULL, p0, 16);
        float u1 = __shfl_xor_sync(FULL, p1, 16);
        float w01 = (lane & 16) ? (p1 + u1) : (p0 + u0);
        float u2 = __shfl_xor_sync(FULL, p2, 16);
        float u3 = __shfl_xor_sync(FULL, p3, 16);
        float w23 = (lane & 16) ? (p3 + u3) : (p2 + u2);
        float v01 = __shfl_xor_sync(FULL, w01, 8);
        float v23 = __shfl_xor_sync(FULL, w23, 8);
        float v = (lane & 8) ? (w23 + v23) : (w01 + v01);
        v += __shfl_xor_sync(FULL, v, 4);
        v += __shfl_xor_sync(FULL, v, 2);
        v += __shfl_xor_sync(FULL, v, 1);
        // v = dot of row (kbase + myrow)

        const float r   = __expf(v);            // non_linearity = exp
        const float dtr = dt * r;
        float w, llc;
        if (mcur) {
            const float E = __expf(dtr);
            w   = __fdividef(dtr, E - 1.0f - EPSF);
            llc = __logf(1.0f - __expf(-dtr) + EPSF);
        } else {
            w   = -dtr;
            llc = -dtr;
        }
        const float pfmy = (myrow == 0) ? pf0 : (myrow == 1) ? pf1
                         : (myrow == 2) ? pf2 : pf3;
        p1acc += pfmy * llc;                    // 8x redundant; /8 at epilogue
        p2acc += pfmy * pfmy * llc;

        const float w0 = __shfl_sync(FULL, w, 0);
        const float w1 = __shfl_sync(FULL, w, 16);
        const float w2 = __shfl_sync(FULL, w, 8);
        const float w3 = __shfl_sync(FULL, w, 24);

        const float a0 = pf0 * w0, a1 = pf1 * w1, a2 = pf2 * w2, a3 = pf3 * w3;
        const float h0 = pf0 * a0, h1 = pf1 * a1, h2 = pf2 * a2, h3 = pf3 * a3;

        Ga0 += a0 * c0.x + a1 * c1.x + a2 * c2.x + a3 * c3.x;
        Ga1 += a0 * c0.y + a1 * c1.y + a2 * c2.y + a3 * c3.y;
        Ga2 += a0 * c0.z + a1 * c1.z + a2 * c2.z + a3 * c3.z;
        Ga3 += a0 * c0.w + a1 * c1.w + a2 * c2.w + a3 * c3.w;
        Ha0 += h0 * c0.x + h1 * c1.x + h2 * c2.x + h3 * c3.x;
        Ha1 += h0 * c0.y + h1 * c1.y + h2 * c2.y + h3 * c3.y;
        Ha2 += h0 * c0.z + h1 * c1.z + h2 * c2.z + h3 * c3.z;
        Ha3 += h0 * c0.w + h1 * c1.w + h2 * c2.w + h3 * c3.w;

        c0 = n0; c1 = n1; c2 = n2; c3 = n3; mcur = mnext;
    }

    #pragma unroll
    for (int o = 16; o; o >>= 1) {
        p1acc += __shfl_xor_sync(FULL, p1acc, o);
        p2acc += __shfl_xor_sync(FULL, p2acc, o);
    }
    p1acc *= 0.125f; p2acc *= 0.125f;

    __shared__ float sga[4][A_DIM];
    __shared__ float sha[4][A_DIM];
    __shared__ float sp[4][2];
    if (lane < 25) {
        *(float4*)&sga[warp][lane * 4] = make_float4(Ga0, Ga1, Ga2, Ga3);
        *(float4*)&sha[warp][lane * 4] = make_float4(Ha0, Ha1, Ha2, Ha3);
    }
    if (lane == 0) { sp[warp][0] = p1acc; sp[warp][1] = p2acc; }
    __syncthreads();

    const int tid = threadIdx.x;
    if (tid < A_DIM) {
        const float ga = sga[0][tid] + sga[1][tid] + sga[2][tid] + sga[3][tid];
        const float ha = sha[0][tid] + sha[1][tid] + sha[2][tid] + sha[3][tid];
        atomicAdd(&d_acc[tid],         ga);
        atomicAdd(&d_acc[A_DIM + tid], ha);
    }
    if (tid == 0)
        atomicAdd(&d_acc[2 * A_DIM],     sp[0][0] + sp[1][0] + sp[2][0] + sp[3][0]);
    if (tid == 1)
        atomicAdd(&d_acc[2 * A_DIM + 1], sp[0][1] + sp[1][1] + sp[2][1] + sp[3][1]);
}

// Rank-1 gramians: only phi moments + accumulated Ga/Ha/P1/P2 remain.
// Reads d_acc into registers, then zeroes it for the next launch/replay.
__global__ __launch_bounds__(128) void mmdglm_finalize(
    const float* __restrict__ phi_d, const float* __restrict__ phi_fr,
    float* __restrict__ out)
{
    __shared__ float shp[4][4];
    __shared__ float sc[4];
    const int tid = threadIdx.x, lane = tid & 31, warp = tid >> 5;
    const unsigned FULL = 0xffffffffu;

    float Ga = 0.f, Ha = 0.f;
    if (tid < A_DIM) { Ga = d_acc[tid]; Ha = d_acc[A_DIM + tid]; }
    const float P1 = d_acc[2 * A_DIM], P2 = d_acc[2 * A_DIM + 1];

    float a0 = 0.f, a1 = 0.f, a2 = 0.f, a3 = 0.f;
    for (int i = tid; i < KFR; i += 128) {
        const float pf = phi_fr[i], pd = phi_d[i];
        a0 += pf; a1 += pf * pf; a2 += pd; a3 += pd * pd;
    }
    #pragma unroll
    for (int o = 16; o; o >>= 1) {
        a0 += __shfl_xor_sync(FULL, a0, o);
        a1 += __shfl_xor_sync(FULL, a1, o);
        a2 += __shfl_xor_sync(FULL, a2, o);
        a3 += __shfl_xor_sync(FULL, a3, o);
    }
    if (lane == 0) { shp[warp][0] = a0; shp[warp][1] = a1;
                     shp[warp][2] = a2; shp[warp][3] = a3; }
    __syncthreads();

    // clean d_acc for the next graph replay (all reads above are done)
    if (tid < A_DIM) { d_acc[tid] = 0.f; d_acc[A_DIM + tid] = 0.f; }
    if (tid == A_DIM) { d_acc[2 * A_DIM] = 0.f; d_acc[2 * A_DIM + 1] = 0.f; }

    if (tid < 4) sc[tid] = shp[0][tid] + shp[1][tid] + shp[2][tid] + shp[3][tid];
    __syncthreads();

    const float S_fr = sc[0], Q_fr = sc[1], S_d = sc[2], Q_d = sc[3];
    const float n_fr = 0.5f * (float)KFR * (float)(KFR - 1);
    const float n_d  = 0.5f * (float)KD  * (float)(KD - 1);
    const float inv_kdkfr = 1.0f / ((float)KD * (float)KFR);

    if (tid == 0) {
        out[0] = (P1 * S_fr - P2) / n_fr - 2.0f * S_d * P1 * inv_kdkfr;
        out[1 + A_DIM] = (S_d * S_d - Q_d) / (2.0f * n_d)
                       + (S_fr * S_fr - Q_fr) / (2.0f * n_fr)
                       - 2.0f * S_d * S_fr * inv_kdkfr;
    }
    if (tid < A_DIM) {
        out[1 + tid] = (S_fr * Ga - Ha) / n_fr - 2.0f * S_d * Ga * inv_kdkfr;
    }
}

extern "C" void kernel_launch(void* const* d_in, const int* in_sizes, int n_in,
                              void* d_out, int out_size) {
    const float* t      = (const float*)d_in[0];
    const int*   mask   = (const int*)  d_in[1];
    const float* X      = (const float*)d_in[2];
    const float* theta  = (const float*)d_in[3];
    const float* phi_d  = (const float*)d_in[4];
    const float* phi_fr = (const float*)d_in[5];
    float* out = (float*)d_out;

    mmdglm_main<<<T_DIM, 128>>>(t, mask, X, theta, phi_fr);
    mmdglm_finalize<<<1, 128>>>(phi_d, phi_fr, out);
}

// round 6
// speedup vs baseline: 1.9443x; 1.0641x over previous
#include <cuda_runtime.h>

#define T_DIM   2000
#define KFR     400
#define KD      400
#define A_DIM   100
#define NB      (KFR / 16)             // 25 batches of 16 rows per slab
#define SLABS   2                      // t-slabs per block
#define GRID    (T_DIM / SLABS)        // 1000 blocks -> exactly one wave
#define NBTOT   (NB * SLABS)           // 50 batches over 2 contiguous slabs
#define EPSF    1e-24f

// Accumulators: [0..99]=Ga, [100..199]=Ha, [200]=P1, [201]=P2.
// Self-cleaning: the last block zeroes after the fused finalize, so every
// launch / graph replay starts from 0 with no memset kernel.
__device__ float d_acc[2 * A_DIM + 2];
__device__ unsigned int d_done;        // last-block-done counter (self-resets)

// One block per pair of adjacent time slabs: a contiguous 320KB region of X
// (rows gr = 0..799 -> t = t0 + gr/400, k = gr%400). Warps sweep adjacent
// 4-row groups so the block's in-flight loads form a sliding window —
// streaming-friendly for HBM. phi_fr folded at row level:
//   Ga[a]=sum pf*w*x, Ha[a]=sum pf^2*w*x, P1=sum pf*llc, P2=sum pf^2*llc.
// Packed butterfly: 9 shfl reduce 4 row-dots into disjoint 8-lane groups so
// exp/log/div run once per group (1 MUFU op serves 4 rows). The last block
// to finish performs the scalar finalize inline (no extra launch).
__global__ __launch_bounds__(128) void mmdglm_main(
    const float* __restrict__ tg, const int* __restrict__ mask,
    const float* __restrict__ X, const float* __restrict__ theta,
    const float* __restrict__ phi_fr, const float* __restrict__ phi_d,
    float* __restrict__ out)
{
    const int warp  = threadIdx.x >> 5;
    const int lane  = threadIdx.x & 31;
    const int tid   = threadIdx.x;
    const float dt  = tg[1] - tg[0];
    const unsigned FULL = 0xffffffffu;

    float4 th = make_float4(0.f, 0.f, 0.f, 0.f);
    if (lane < 25) th = __ldg(((const float4*)theta) + lane);

    // packed-butterfly group -> row: lanes 0-7 r0, 8-15 r2, 16-23 r1, 24-31 r3
    const int myrow = (((lane >> 3) & 1) << 1) | ((lane >> 4) & 1);

    float Ga0 = 0.f, Ga1 = 0.f, Ga2 = 0.f, Ga3 = 0.f;
    float Ha0 = 0.f, Ha1 = 0.f, Ha2 = 0.f, Ha3 = 0.f;
    float p1acc = 0.f, p2acc = 0.f;

    // contiguous 320KB region: slabs t0 and t0+1
    const float* slab = X    + (size_t)(blockIdx.x * SLABS) * KFR * A_DIM;
    const int*   mrow = mask + (size_t)(blockIdx.x * SLABS) * KFR;

    // prefetch batch 0
    float4 z = make_float4(0.f, 0.f, 0.f, 0.f);
    float4 c0 = z, c1 = z, c2 = z, c3 = z;
    {
        const float* rowp = slab + (warp * 4) * A_DIM;
        if (lane < 25) {
            c0 = __ldg((const float4*)(rowp)             + lane);
            c1 = __ldg((const float4*)(rowp + A_DIM)     + lane);
            c2 = __ldg((const float4*)(rowp + 2 * A_DIM) + lane);
            c3 = __ldg((const float4*)(rowp + 3 * A_DIM) + lane);
        }
    }
    int mcur = __ldg(mrow + warp * 4 + myrow);

    #pragma unroll 1
    for (int g = 0; g < NBTOT; g++) {
        const int grbase = g * 16 + warp * 4;          // global row 0..799

        float4 n0 = z, n1 = z, n2 = z, n3 = z;
        int mnext = 0;
        if (g + 1 < NBTOT) {
            const int grn = grbase + 16;
            const float* rowp = slab + (size_t)grn * A_DIM;
            if (lane < 25) {
                n0 = __ldg((const float4*)(rowp)             + lane);
                n1 = __ldg((const float4*)(rowp + A_DIM)     + lane);
                n2 = __ldg((const float4*)(rowp + 2 * A_DIM) + lane);
                n3 = __ldg((const float4*)(rowp + 3 * A_DIM) + lane);
            }
            mnext = __ldg(mrow + grn + myrow);
        }

        // k index for phi (row mod KFR); L1-resident 1.6KB table
        const int kbase = (grbase >= KFR) ? (grbase - KFR) : grbase;
        const float pf0 = __ldg(phi_fr + kbase);
        const float pf1 = __ldg(phi_fr + kbase + 1);
        const float pf2 = __ldg(phi_fr + kbase + 2);
        const float pf3 = __ldg(phi_fr + kbase + 3);

        float p0 = c0.x * th.x + c0.y * th.y + c0.z * th.z + c0.w * th.w;
        float p1 = c1.x * th.x + c1.y * th.y + c1.z * th.z + c1.w * th.w;
        float p2 = c2.x * th.x + c2.y * th.y + c2.z * th.z + c2.w * th.w;
        float p3 = c3.x * th.x + c3.y * th.y + c3.z * th.z + c3.w * th.w;

        // Packed butterfly: 9 shfl reduce all 4 rows.
        float u0 = __shfl_xor_sync(FULL, p0, 16);
        float u1 = __shfl_xor_sync(FULL, p1, 16);
        float w01 = (lane & 16) ? (p1 + u1) : (p0 + u0);
        float u2 = __shfl_xor_sync(FULL, p2, 16);
        float u3 = __shfl_xor_sync(FULL, p3, 16);
        float w23 = (lane & 16) ? (p3 + u3) : (p2 + u2);
        float v01 = __shfl_xor_sync(FULL, w01, 8);
        float v23 = __shfl_xor_sync(FULL, w23, 8);
        float v = (lane & 8) ? (w23 + v23) : (w01 + v01);
        v += __shfl_xor_sync(FULL, v, 4);
        v += __shfl_xor_sync(FULL, v, 2);
        v += __shfl_xor_sync(FULL, v, 1);
        // v = dot of row (grbase + myrow)

        const float r   = __expf(v);            // non_linearity = exp
        const float dtr = dt * r;
        float w, llc;
        if (mcur) {
            const float E = __expf(dtr);
            w   = __fdividef(dtr, E - 1.0f - EPSF);
            llc = __logf(1.0f - __expf(-dtr) + EPSF);
        } else {
            w   = -dtr;
            llc = -dtr;
        }
        const float pfmy = (myrow == 0) ? pf0 : (myrow == 1) ? pf1
                         : (myrow == 2) ? pf2 : pf3;
        p1acc += pfmy * llc;                    // 8x redundant; /8 at epilogue
        p2acc += pfmy * pfmy * llc;

        const float w0 = __shfl_sync(FULL, w, 0);
        const float w1 = __shfl_sync(FULL, w, 16);
        const float w2 = __shfl_sync(FULL, w, 8);
        const float w3 = __shfl_sync(FULL, w, 24);

        const float a0 = pf0 * w0, a1 = pf1 * w1, a2 = pf2 * w2, a3 = pf3 * w3;
        const float h0 = pf0 * a0, h1 = pf1 * a1, h2 = pf2 * a2, h3 = pf3 * a3;

        Ga0 += a0 * c0.x + a1 * c1.x + a2 * c2.x + a3 * c3.x;
        Ga1 += a0 * c0.y + a1 * c1.y + a2 * c2.y + a3 * c3.y;
        Ga2 += a0 * c0.z + a1 * c1.z + a2 * c2.z + a3 * c3.z;
        Ga3 += a0 * c0.w + a1 * c1.w + a2 * c2.w + a3 * c3.w;
        Ha0 += h0 * c0.x + h1 * c1.x + h2 * c2.x + h3 * c3.x;
        Ha1 += h0 * c0.y + h1 * c1.y + h2 * c2.y + h3 * c3.y;
        Ha2 += h0 * c0.z + h1 * c1.z + h2 * c2.z + h3 * c3.z;
        Ha3 += h0 * c0.w + h1 * c1.w + h2 * c2.w + h3 * c3.w;

        c0 = n0; c1 = n1; c2 = n2; c3 = n3; mcur = mnext;
    }

    #pragma unroll
    for (int o = 16; o; o >>= 1) {
        p1acc += __shfl_xor_sync(FULL, p1acc, o);
        p2acc += __shfl_xor_sync(FULL, p2acc, o);
    }
    p1acc *= 0.125f; p2acc *= 0.125f;

    __shared__ float sga[4][A_DIM];
    __shared__ float sha[4][A_DIM];
    __shared__ float sp[4][2];
    if (lane < 25) {
        *(float4*)&sga[warp][lane * 4] = make_float4(Ga0, Ga1, Ga2, Ga3);
        *(float4*)&sha[warp][lane * 4] = make_float4(Ha0, Ha1, Ha2, Ha3);
    }
    if (lane == 0) { sp[warp][0] = p1acc; sp[warp][1] = p2acc; }
    __syncthreads();

    if (tid < A_DIM) {
        const float ga = sga[0][tid] + sga[1][tid] + sga[2][tid] + sga[3][tid];
        const float ha = sha[0][tid] + sha[1][tid] + sha[2][tid] + sha[3][tid];
        atomicAdd(&d_acc[tid],         ga);
        atomicAdd(&d_acc[A_DIM + tid], ha);
    }
    if (tid == 0)
        atomicAdd(&d_acc[2 * A_DIM],     sp[0][0] + sp[1][0] + sp[2][0] + sp[3][0]);
    if (tid == 1)
        atomicAdd(&d_acc[2 * A_DIM + 1], sp[0][1] + sp[1][1] + sp[2][1] + sp[3][1]);

    // ---- last-block-done fused finalize ----
    __threadfence();
    __shared__ bool amlast;
    if (tid == 0) amlast = (atomicAdd(&d_done, 1u) == (unsigned)(gridDim.x - 1));
    __syncthreads();
    if (!amlast) return;

    // snapshot accumulators (volatile: bypass L1, see all L2 atomics)
    volatile float* vacc = d_acc;
    float Ga = 0.f, Ha = 0.f;
    if (tid < A_DIM) { Ga = vacc[tid]; Ha = vacc[A_DIM + tid]; }
    const float P1 = vacc[2 * A_DIM], P2 = vacc[2 * A_DIM + 1];

    // phi moments
    float b0 = 0.f, b1 = 0.f, b2 = 0.f, b3 = 0.f;
    for (int i = tid; i < KFR; i += 128) {
        const float pfv = phi_fr[i], pdv = phi_d[i];
        b0 += pfv; b1 += pfv * pfv; b2 += pdv; b3 += pdv * pdv;
    }
    #pragma unroll
    for (int o = 16; o; o >>= 1) {
        b0 += __shfl_xor_sync(FULL, b0, o);
        b1 += __shfl_xor_sync(FULL, b1, o);
        b2 += __shfl_xor_sync(FULL, b2, o);
        b3 += __shfl_xor_sync(FULL, b3, o);
    }
    __shared__ float shp[4][4];
    __shared__ float sc[4];
    if (lane == 0) { shp[warp][0] = b0; shp[warp][1] = b1;
                     shp[warp][2] = b2; shp[warp][3] = b3; }
    __syncthreads();

    // clean state for the next graph replay (all d_acc reads are done)
    if (tid < A_DIM) { d_acc[tid] = 0.f; d_acc[A_DIM + tid] = 0.f; }
    if (tid == A_DIM) { d_acc[2 * A_DIM] = 0.f; d_acc[2 * A_DIM + 1] = 0.f;
                        d_done = 0u; }

    if (tid < 4) sc[tid] = shp[0][tid] + shp[1][tid] + shp[2][tid] + shp[3][tid];
    __syncthreads();

    const float S_fr = sc[0], Q_fr = sc[1], S_d = sc[2], Q_d = sc[3];
    const float n_fr = 0.5f * (float)KFR * (float)(KFR - 1);
    const float n_d  = 0.5f * (float)KD  * (float)(KD - 1);
    const float inv_kdkfr = 1.0f / ((float)KD * (float)KFR);

    if (tid == 0) {
        out[0] = (P1 * S_fr - P2) / n_fr - 2.0f * S_d * P1 * inv_kdkfr;
        out[1 + A_DIM] = (S_d * S_d - Q_d) / (2.0f * n_d)
                       + (S_fr * S_fr - Q_fr) / (2.0f * n_fr)
                       - 2.0f * S_d * S_fr * inv_kdkfr;
    }
    if (tid < A_DIM) {
        out[1 + tid] = (S_fr * Ga - Ha) / n_fr - 2.0f * S_d * Ga * inv_kdkfr;
    }
}

extern "C" void kernel_launch(void* const* d_in, const int* in_sizes, int n_in,
                              void* d_out, int out_size) {
    const float* t      = (const float*)d_in[0];
    const int*   mask   = (const int*)  d_in[1];
    const float* X      = (const float*)d_in[2];
    const float* theta  = (const float*)d_in[3];
    const float* phi_d  = (const float*)d_in[4];
    const float* phi_fr = (const float*)d_in[5];
    float* out = (float*)d_out;

    mmdglm_main<<<GRID, 128>>>(t, mask, X, theta, phi_fr, phi_d, out);
}